// round 6
// baseline (speedup 1.0000x reference)
#include <cuda_runtime.h>
#include <cstdint>

#define BB 4
#define TT 4096
#define CC 768
#define HH 64
#define M_TOT (BB*TT)
#define KS 4
#define NQT 64            // 64-row q-tiles per batch

// ---------------- tf32 mma.sync helpers ----------------
__device__ __forceinline__ uint32_t tf32r(float f) {
    uint32_t r;
    asm("cvt.rna.tf32.f32 %0, %1;" : "=r"(r) : "f"(f));
    return r;
}
__device__ __forceinline__ void mma8(float c[4], uint32_t a0, uint32_t a1,
                                     uint32_t a2, uint32_t a3,
                                     uint32_t b0, uint32_t b1) {
    asm volatile(
        "mma.sync.aligned.m16n8k8.row.col.f32.tf32.tf32.f32 "
        "{%0,%1,%2,%3}, {%4,%5,%6,%7}, {%8,%9}, {%0,%1,%2,%3};"
        : "+f"(c[0]), "+f"(c[1]), "+f"(c[2]), "+f"(c[3])
        : "r"(a0), "r"(a1), "r"(a2), "r"(a3), "r"(b0), "r"(b1));
}
__device__ __forceinline__ float ex2(float x) {
    float r;
    asm("ex2.approx.f32 %0, %1;" : "=f"(r) : "f"(x));
    return r;
}

// ---------------- global scratch ----------------
__device__ float g_q[M_TOT*HH];     // pre-scaled by log2(e)/8
__device__ float g_k[M_TOT*HH];
__device__ float g_v[M_TOT*HH];
__device__ float g_pacc[(size_t)BB*NQT*KS*64*64];   // 16.8 MB partial accumulators
__device__ float g_pl[BB*NQT*KS*64];                // partial row sums

// ---------------------------------------------------------------------------
// Kernel 1: FUSED QKV projection via tf32 mma.sync.
// One CTA = 64 x-rows; computes all 192 output cols (K|Q|V) so X is staged
// and converted once (X DRAM traffic 48MB instead of 144MB).
// grid (M_TOT/64), 256 thr, 8 warps: warp = (ms 0..3 m-tile, nh 0..1 96-col half).
// Xs[64][36]: A-frag loads bank-free. Ws[32][200]: stride%32==8 -> B-frags bank-free.
// ---------------------------------------------------------------------------
__global__ __launch_bounds__(256)
void proj_kernel(const float* __restrict__ x,
                 const float* __restrict__ Wk,
                 const float* __restrict__ Wq,
                 const float* __restrict__ Wv) {
    __shared__ float Xs[64*36];
    __shared__ float Ws[32*200];

    const int m0   = blockIdx.x * 64;
    const int tid  = threadIdx.x;
    const int wid  = tid >> 5;
    const int lane = tid & 31;
    const int g    = lane >> 2;
    const int t    = lane & 3;
    const int ms   = wid >> 1;
    const int nb   = (wid & 1) * 96;

    float oc[12][4];
#pragma unroll
    for (int i = 0; i < 12; i++)
#pragma unroll
        for (int j = 0; j < 4; j++) oc[i][j] = 0.f;

    for (int k0 = 0; k0 < CC; k0 += 32) {
        // stage X (tf32-rounded): 64 rows x 32 cols
#pragma unroll
        for (int it = 0; it < 2; it++) {
            int idx = it * 256 + tid;
            int row = idx >> 3;
            int f4  = (idx & 7) * 4;
            float4 v = *(const float4*)&x[(size_t)(m0 + row) * CC + k0 + f4];
            uint4 u = make_uint4(tf32r(v.x), tf32r(v.y), tf32r(v.z), tf32r(v.w));
            *(uint4*)&Xs[row * 36 + f4] = u;
        }
        // stage all three W chunks: 32 k-rows x 192 cols (K|Q|V)
#pragma unroll
        for (int it = 0; it < 6; it++) {
            int idx = it * 256 + tid;     // 0..1535
            int row = idx / 48;
            int cw  = idx % 48;
            int which = cw >> 4;
            int h4  = (cw & 15) * 4;
            const float* Wp = (which == 0) ? Wk : ((which == 1) ? Wq : Wv);
            float4 v = *(const float4*)&Wp[(size_t)(k0 + row) * HH + h4];
            uint4 u = make_uint4(tf32r(v.x), tf32r(v.y), tf32r(v.z), tf32r(v.w));
            *(uint4*)&Ws[row * 200 + which * 64 + h4] = u;
        }
        __syncthreads();

        const uint32_t* Xu = (const uint32_t*)Xs;
        const uint32_t* Wu = (const uint32_t*)Ws;
#pragma unroll
        for (int kk = 0; kk < 4; kk++) {
            uint32_t a0 = Xu[(ms * 16 + g) * 36 + kk * 8 + t];
            uint32_t a1 = Xu[(ms * 16 + g + 8) * 36 + kk * 8 + t];
            uint32_t a2 = Xu[(ms * 16 + g) * 36 + kk * 8 + t + 4];
            uint32_t a3 = Xu[(ms * 16 + g + 8) * 36 + kk * 8 + t + 4];
#pragma unroll
            for (int nt = 0; nt < 12; nt++) {
                uint32_t b0 = Wu[(kk * 8 + t) * 200 + nb + nt * 8 + g];
                uint32_t b1 = Wu[(kk * 8 + t + 4) * 200 + nb + nt * 8 + g];
                mma8(oc[nt], a0, a1, a2, a3, b0, b1);
            }
        }
        __syncthreads();
    }

    // epilogue: route each 8-col n-tile to K/Q/V with per-matrix scale
    const int r0 = m0 + ms * 16 + g;
#pragma unroll
    for (int nt = 0; nt < 12; nt++) {
        int gc = nb + nt * 8 + 2 * t;
        int which = gc >> 6;
        int col = gc & 63;
        float sc = (which == 1) ? 0.18033688011112042f : 1.0f;   // log2(e)/8 on q
        float* op = (which == 0) ? g_k : ((which == 1) ? g_q : g_v);
        *(float2*)&op[(size_t)r0 * HH + col] =
            make_float2(oc[nt][0] * sc, oc[nt][1] * sc);
        *(float2*)&op[(size_t)(r0 + 8) * HH + col] =
            make_float2(oc[nt][2] * sc, oc[nt][3] * sc);
    }
}

// ---------------------------------------------------------------------------
// Kernel 2: tf32 mma.sync flash attention partials (fixed-offset softmax,
// no rescale) with software-pipelined K/V staging: next chunk's K/V are
// prefetched into registers during this chunk's MMAs, stored after GEMM2.
// CTA = (batch, 64-row q-tile, key-split). 8 warps: 16m x 32n slabs.
// ---------------------------------------------------------------------------
#define ATTN_SMEM ((64*68 + 64*72 + 64*68 + 128) * 4)

__global__ __launch_bounds__(256, 2)
void attn_kernel() {
    extern __shared__ float sm[];
    float* Ks   = sm;                 // [n][h] stride 68
    float* Vs   = Ks + 64 * 68;       // [s][h] stride 72
    float* Ps   = Vs + 64 * 72;       // [m][s] stride 68 (Q staging pre-loop)
    float* lbuf = Ps + 64 * 68;       // [2][64]

    const int tid  = threadIdx.x;
    const int wid  = tid >> 5;
    const int lane = tid & 31;
    const int g    = lane >> 2;
    const int t    = lane & 3;
    const int ms   = wid >> 1;
    const int nh   = wid & 1;
    const int nb   = nh * 32;
    const int r0   = ms * 16 + g;     // local rows r0, r0+8

    const int b     = blockIdx.y;
    const int qt    = NQT - 1 - (blockIdx.x >> 2);   // heavy tiles first
    const int split = blockIdx.x & (KS - 1);
    const int q0    = qt * 64;
    const int nch   = qt + 1;
    const int lo    = (split * nch) / KS;
    const int hi    = ((split + 1) * nch) / KS;
    const size_t slot = (size_t)(b * NQT + qt) * KS + split;
    float* pa = g_pacc + slot * 4096;

    if (lo >= hi) {   // empty split: zero partials
        float4 z = make_float4(0.f, 0.f, 0.f, 0.f);
        for (int e = tid; e < 1024; e += 256) ((float4*)pa)[e] = z;
        if (tid < 64) g_pl[slot * 64 + tid] = 0.f;
        return;
    }

    const float* qp = g_q + (size_t)b * TT * HH;
    const float* kp = g_k + (size_t)b * TT * HH;
    const float* vp = g_v + (size_t)b * TT * HH;

    // Stage Q (tf32-rounded) into Ps region, then load register fragments.
#pragma unroll
    for (int it = 0; it < 4; it++) {
        int idx = it * 256 + tid;
        int n  = idx >> 4;
        int h4 = (idx & 15) * 4;
        float4 v = *(const float4*)&qp[(size_t)(q0 + n) * HH + h4];
        uint4 u = make_uint4(tf32r(v.x), tf32r(v.y), tf32r(v.z), tf32r(v.w));
        *(uint4*)&Ps[n * 68 + h4] = u;
    }
    __syncthreads();

    uint32_t qa[8][4];
    {
        const uint32_t* Pu = (const uint32_t*)Ps;
#pragma unroll
        for (int kk = 0; kk < 8; kk++) {
            qa[kk][0] = Pu[r0 * 68 + kk * 8 + t];
            qa[kk][1] = Pu[(r0 + 8) * 68 + kk * 8 + t];
            qa[kk][2] = Pu[r0 * 68 + kk * 8 + t + 4];
            qa[kk][3] = Pu[(r0 + 8) * 68 + kk * 8 + t + 4];
        }
    }
    __syncthreads();   // Q frag reads done before Ps is overwritten by softmax

    // Stage first chunk's K/V
    {
        const int s0 = lo * 64;
#pragma unroll
        for (int it = 0; it < 4; it++) {
            int idx = it * 256 + tid;
            int n  = idx >> 4;
            int h4 = (idx & 15) * 4;
            float4 kv = *(const float4*)&kp[(size_t)(s0 + n) * HH + h4];
            *(uint4*)&Ks[n * 68 + h4] =
                make_uint4(tf32r(kv.x), tf32r(kv.y), tf32r(kv.z), tf32r(kv.w));
            float4 vv = *(const float4*)&vp[(size_t)(s0 + n) * HH + h4];
            *(uint4*)&Vs[n * 72 + h4] =
                make_uint4(tf32r(vv.x), tf32r(vv.y), tf32r(vv.z), tf32r(vv.w));
        }
    }
    __syncthreads();

    float oc[4][4];
#pragma unroll
    for (int i = 0; i < 4; i++)
#pragma unroll
        for (int j = 0; j < 4; j++) oc[i][j] = 0.f;
    float lr0 = 0.f, lr1 = 0.f;

    for (int ck = lo; ck < hi; ck++) {
        // prefetch next chunk's K/V into registers (latency hidden by MMAs)
        float4 pk[4], pv[4];
        const bool pre = (ck + 1 < hi);
        if (pre) {
            const int s1 = (ck + 1) * 64;
#pragma unroll
            for (int it = 0; it < 4; it++) {
                int idx = it * 256 + tid;
                int n  = idx >> 4;
                int h4 = (idx & 15) * 4;
                pk[it] = *(const float4*)&kp[(size_t)(s1 + n) * HH + h4];
                pv[it] = *(const float4*)&vp[(size_t)(s1 + n) * HH + h4];
            }
        }

        // GEMM1: S[m][n] = Q x K^T (k = h = 64 -> 8 k-steps)
        float sc[4][4];
#pragma unroll
        for (int i = 0; i < 4; i++)
#pragma unroll
            for (int j = 0; j < 4; j++) sc[i][j] = 0.f;

        const uint32_t* Ku = (const uint32_t*)Ks;
#pragma unroll
        for (int kk = 0; kk < 8; kk++) {
#pragma unroll
            for (int nt = 0; nt < 4; nt++) {
                uint32_t b0 = Ku[(nb + nt * 8 + g) * 68 + kk * 8 + t];
                uint32_t b1 = Ku[(nb + nt * 8 + g) * 68 + kk * 8 + t + 4];
                mma8(sc[nt], qa[kk][0], qa[kk][1], qa[kk][2], qa[kk][3], b0, b1);
            }
        }

        // softmax: P = exp2(S) with causal mask on diagonal chunk
        const int diag = (ck == qt);
#pragma unroll
        for (int nt = 0; nt < 4; nt++) {
            int c0 = nb + nt * 8 + 2 * t;
            float p0 = ex2(sc[nt][0]);
            float p1 = ex2(sc[nt][1]);
            float p2 = ex2(sc[nt][2]);
            float p3 = ex2(sc[nt][3]);
            if (diag) {
                if (c0 > r0)     p0 = 0.f;
                if (c0 + 1 > r0) p1 = 0.f;
                if (c0 > r0 + 8)     p2 = 0.f;
                if (c0 + 1 > r0 + 8) p3 = 0.f;
            }
            uint32_t u0 = tf32r(p0), u1 = tf32r(p1), u2 = tf32r(p2), u3 = tf32r(p3);
            lr0 += __uint_as_float(u0) + __uint_as_float(u1);
            lr1 += __uint_as_float(u2) + __uint_as_float(u3);
            *(uint2*)&Ps[r0 * 68 + c0]       = make_uint2(u0, u1);
            *(uint2*)&Ps[(r0 + 8) * 68 + c0] = make_uint2(u2, u3);
        }
        __syncthreads();   // all P visible before cross-warp GEMM2

        // GEMM2: O[m][h] += P x V (k = s = 64 -> 8 k-steps)
        const uint32_t* Pu = (const uint32_t*)Ps;
        const uint32_t* Vu = (const uint32_t*)Vs;
#pragma unroll
        for (int kk = 0; kk < 8; kk++) {
            uint32_t a0 = Pu[r0 * 68 + kk * 8 + t];
            uint32_t a1 = Pu[(r0 + 8) * 68 + kk * 8 + t];
            uint32_t a2 = Pu[r0 * 68 + kk * 8 + t + 4];
            uint32_t a3 = Pu[(r0 + 8) * 68 + kk * 8 + t + 4];
#pragma unroll
            for (int nt = 0; nt < 4; nt++) {
                uint32_t b0 = Vu[(kk * 8 + t) * 72 + nb + nt * 8 + g];
                uint32_t b1 = Vu[(kk * 8 + t + 4) * 72 + nb + nt * 8 + g];
                mma8(oc[nt], a0, a1, a2, a3, b0, b1);
            }
        }
        __syncthreads();   // GEMM2 reads done before restaging K/V

        if (pre) {
#pragma unroll
            for (int it = 0; it < 4; it++) {
                int idx = it * 256 + tid;
                int n  = idx >> 4;
                int h4 = (idx & 15) * 4;
                *(uint4*)&Ks[n * 68 + h4] =
                    make_uint4(tf32r(pk[it].x), tf32r(pk[it].y), tf32r(pk[it].z), tf32r(pk[it].w));
                *(uint4*)&Vs[n * 72 + h4] =
                    make_uint4(tf32r(pv[it].x), tf32r(pv[it].y), tf32r(pv[it].z), tf32r(pv[it].w));
            }
            __syncthreads();
        }
    }

    // row-sum reduction: across 4 lanes of the group, then across n-half warps
    lr0 += __shfl_xor_sync(0xffffffffu, lr0, 1);
    lr0 += __shfl_xor_sync(0xffffffffu, lr0, 2);
    lr1 += __shfl_xor_sync(0xffffffffu, lr1, 1);
    lr1 += __shfl_xor_sync(0xffffffffu, lr1, 2);
    if (t == 0) {
        lbuf[nh * 64 + r0]     = lr0;
        lbuf[nh * 64 + r0 + 8] = lr1;
    }
    __syncthreads();

    // write partials
#pragma unroll
    for (int nt = 0; nt < 4; nt++) {
        int col = nb + nt * 8 + 2 * t;
        *(float2*)&pa[r0 * 64 + col]       = make_float2(oc[nt][0], oc[nt][1]);
        *(float2*)&pa[(r0 + 8) * 64 + col] = make_float2(oc[nt][2], oc[nt][3]);
    }
    if (tid < 64) g_pl[slot * 64 + tid] = lbuf[tid] + lbuf[64 + tid];
}

// ---------------------------------------------------------------------------
// Kernel 3: merge key-split partials (plain sums) and normalize.
// ---------------------------------------------------------------------------
__global__ __launch_bounds__(256)
void combine_kernel(float* __restrict__ out) {
    const int qt = blockIdx.x;
    const int b  = blockIdx.y;
    const int tid = threadIdx.x;
    const size_t base = (size_t)(b * NQT + qt) * KS;

    __shared__ float ls[64];
    if (tid < 64) {
        float s = 0.f;
#pragma unroll
        for (int sp = 0; sp < KS; sp++) s += g_pl[(base + sp) * 64 + tid];
        ls[tid] = 1.0f / s;
    }
    __syncthreads();

    for (int e = tid; e < 1024; e += 256) {
        const int row = e >> 4;
        float4 a = make_float4(0.f, 0.f, 0.f, 0.f);
#pragma unroll
        for (int sp = 0; sp < KS; sp++) {
            float4 v = ((const float4*)(g_pacc + (base + sp) * 4096))[e];
            a.x += v.x; a.y += v.y; a.z += v.z; a.w += v.w;
        }
        const float inv = ls[row];
        a.x *= inv; a.y *= inv; a.z *= inv; a.w *= inv;
        *(float4*)&out[((size_t)b * TT + qt * 64 + row) * HH + (e & 15) * 4] = a;
    }
}

extern "C" void kernel_launch(void* const* d_in, const int* in_sizes, int n_in,
                              void* d_out, int out_size) {
    const float* x  = (const float*)d_in[0];
    const float* Wk = (const float*)d_in[1];
    const float* Wq = (const float*)d_in[2];
    const float* Wv = (const float*)d_in[3];
    float* out = (float*)d_out;

    proj_kernel<<<dim3(M_TOT / 64), 256>>>(x, Wk, Wq, Wv);

    cudaFuncSetAttribute(attn_kernel,
                         cudaFuncAttributeMaxDynamicSharedMemorySize, ATTN_SMEM);
    attn_kernel<<<dim3(NQT * KS, BB), 256, ATTN_SMEM>>>();

    combine_kernel<<<dim3(NQT, BB), 256>>>(out);
}

// round 7
// speedup vs baseline: 1.2206x; 1.2206x over previous
#include <cuda_runtime.h>
#include <cstdint>

#define BB 4
#define TT 4096
#define CC 768
#define HH 64
#define M_TOT (BB*TT)
#define KS 4
#define NQT 64            // 64-row q-tiles per batch

// ---------------- tf32 mma.sync helpers ----------------
__device__ __forceinline__ uint32_t tf32r(float f) {
    uint32_t r;
    asm("cvt.rna.tf32.f32 %0, %1;" : "=r"(r) : "f"(f));
    return r;
}
__device__ __forceinline__ void mma8(float c[4], uint32_t a0, uint32_t a1,
                                     uint32_t a2, uint32_t a3,
                                     uint32_t b0, uint32_t b1) {
    asm volatile(
        "mma.sync.aligned.m16n8k8.row.col.f32.tf32.tf32.f32 "
        "{%0,%1,%2,%3}, {%4,%5,%6,%7}, {%8,%9}, {%0,%1,%2,%3};"
        : "+f"(c[0]), "+f"(c[1]), "+f"(c[2]), "+f"(c[3])
        : "r"(a0), "r"(a1), "r"(a2), "r"(a3), "r"(b0), "r"(b1));
}
__device__ __forceinline__ float ex2(float x) {
    float r;
    asm("ex2.approx.f32 %0, %1;" : "=f"(r) : "f"(x));
    return r;
}

// ---------------- global scratch ----------------
__device__ float g_q[M_TOT*HH];     // pre-scaled by log2(e)/8
__device__ float g_k[M_TOT*HH];
__device__ float g_v[M_TOT*HH];
__device__ float g_pacc[(size_t)BB*NQT*KS*64*64];   // 16.8 MB partial accumulators
__device__ float g_pl[BB*NQT*KS*64];                // partial row sums

// ---------------------------------------------------------------------------
// Kernel 1: QKV projection via tf32 mma.sync (un-fused: grid (M_TOT/64, 3)
// for occupancy) with register-prefetch pipelining of the next k-chunk.
// BM=64, N=64, KC=32. Warp w: rows 16*(w>>1), cols 32*(w&1).
// Xs[64][36]: A-frag loads bank-free. Wss[32][72]: B-frag loads bank-free.
// ---------------------------------------------------------------------------
__global__ __launch_bounds__(256)
void proj_kernel(const float* __restrict__ x,
                 const float* __restrict__ Wk,
                 const float* __restrict__ Wq,
                 const float* __restrict__ Wv) {
    __shared__ float Xs[64*36];
    __shared__ float Wss[32*72];

    const float* W;
    float* out;
    float scale;
    if (blockIdx.y == 0)      { W = Wk; out = g_k; scale = 1.0f; }
    else if (blockIdx.y == 1) { W = Wq; out = g_q; scale = 0.18033688011112042f; } // log2(e)/8
    else                      { W = Wv; out = g_v; scale = 1.0f; }

    const int m0   = blockIdx.x * 64;
    const int tid  = threadIdx.x;
    const int wid  = tid >> 5;
    const int lane = tid & 31;
    const int g    = lane >> 2;
    const int t    = lane & 3;
    const int ms   = wid >> 1;
    const int nb   = (wid & 1) * 32;

    // staging coordinates (constant per thread)
    const int xrow0 = tid >> 3;            // X: idx = it*256+tid
    const int xf0   = (tid & 7) * 4;
    const int wrow0 = tid >> 4;            // W
    const int wh0   = (tid & 15) * 4;

    float oc[4][4];
#pragma unroll
    for (int i = 0; i < 4; i++)
#pragma unroll
        for (int j = 0; j < 4; j++) oc[i][j] = 0.f;

    // stage chunk 0
#pragma unroll
    for (int it = 0; it < 2; it++) {
        float4 v = *(const float4*)&x[(size_t)(m0 + xrow0 + it * 32) * CC + xf0];
        *(uint4*)&Xs[(xrow0 + it * 32) * 36 + xf0] =
            make_uint4(tf32r(v.x), tf32r(v.y), tf32r(v.z), tf32r(v.w));
        float4 w = *(const float4*)&W[(size_t)(wrow0 + it * 16) * HH + wh0];
        *(uint4*)&Wss[(wrow0 + it * 16) * 72 + wh0] =
            make_uint4(tf32r(w.x), tf32r(w.y), tf32r(w.z), tf32r(w.w));
    }
    __syncthreads();

    for (int k0 = 0; k0 < CC; k0 += 32) {
        // prefetch next chunk into registers (hidden behind MMAs)
        const bool pre = (k0 + 32 < CC);
        float4 px[2], pw[2];
        if (pre) {
#pragma unroll
            for (int it = 0; it < 2; it++) {
                px[it] = *(const float4*)&x[(size_t)(m0 + xrow0 + it * 32) * CC + k0 + 32 + xf0];
                pw[it] = *(const float4*)&W[(size_t)(k0 + 32 + wrow0 + it * 16) * HH + wh0];
            }
        }

        const uint32_t* Xu = (const uint32_t*)Xs;
        const uint32_t* Wu = (const uint32_t*)Wss;
#pragma unroll
        for (int kk = 0; kk < 4; kk++) {
            uint32_t a0 = Xu[(ms * 16 + g) * 36 + kk * 8 + t];
            uint32_t a1 = Xu[(ms * 16 + g + 8) * 36 + kk * 8 + t];
            uint32_t a2 = Xu[(ms * 16 + g) * 36 + kk * 8 + t + 4];
            uint32_t a3 = Xu[(ms * 16 + g + 8) * 36 + kk * 8 + t + 4];
#pragma unroll
            for (int nt = 0; nt < 4; nt++) {
                uint32_t b0 = Wu[(kk * 8 + t) * 72 + nb + nt * 8 + g];
                uint32_t b1 = Wu[(kk * 8 + t + 4) * 72 + nb + nt * 8 + g];
                mma8(oc[nt], a0, a1, a2, a3, b0, b1);
            }
        }

        if (pre) {
            __syncthreads();   // MMA reads done before overwrite
#pragma unroll
            for (int it = 0; it < 2; it++) {
                *(uint4*)&Xs[(xrow0 + it * 32) * 36 + xf0] =
                    make_uint4(tf32r(px[it].x), tf32r(px[it].y), tf32r(px[it].z), tf32r(px[it].w));
                *(uint4*)&Wss[(wrow0 + it * 16) * 72 + wh0] =
                    make_uint4(tf32r(pw[it].x), tf32r(pw[it].y), tf32r(pw[it].z), tf32r(pw[it].w));
            }
            __syncthreads();
        }
    }

#pragma unroll
    for (int nt = 0; nt < 4; nt++) {
        int col = nb + nt * 8 + 2 * t;
        int r0 = m0 + ms * 16 + g;
        *(float2*)&out[(size_t)r0 * HH + col] =
            make_float2(oc[nt][0] * scale, oc[nt][1] * scale);
        *(float2*)&out[(size_t)(r0 + 8) * HH + col] =
            make_float2(oc[nt][2] * scale, oc[nt][3] * scale);
    }
}

// ---------------------------------------------------------------------------
// Kernel 2: tf32 mma.sync flash attention partials (fixed-offset softmax,
// no rescale) with software-pipelined K/V staging (unchanged from R6 — it
// was a ~20us win).
// CTA = (batch, 64-row q-tile, key-split). 8 warps: 16m x 32n slabs.
// ---------------------------------------------------------------------------
#define ATTN_SMEM ((64*68 + 64*72 + 64*68 + 128) * 4)

__global__ __launch_bounds__(256, 2)
void attn_kernel() {
    extern __shared__ float sm[];
    float* Ks   = sm;                 // [n][h] stride 68
    float* Vs   = Ks + 64 * 68;       // [s][h] stride 72
    float* Ps   = Vs + 64 * 72;       // [m][s] stride 68 (Q staging pre-loop)
    float* lbuf = Ps + 64 * 68;       // [2][64]

    const int tid  = threadIdx.x;
    const int wid  = tid >> 5;
    const int lane = tid & 31;
    const int g    = lane >> 2;
    const int t    = lane & 3;
    const int ms   = wid >> 1;
    const int nh   = wid & 1;
    const int nb   = nh * 32;
    const int r0   = ms * 16 + g;     // local rows r0, r0+8

    const int b     = blockIdx.y;
    const int qt    = NQT - 1 - (blockIdx.x >> 2);   // heavy tiles first
    const int split = blockIdx.x & (KS - 1);
    const int q0    = qt * 64;
    const int nch   = qt + 1;
    const int lo    = (split * nch) / KS;
    const int hi    = ((split + 1) * nch) / KS;
    const size_t slot = (size_t)(b * NQT + qt) * KS + split;
    float* pa = g_pacc + slot * 4096;

    if (lo >= hi) {   // empty split: zero partials
        float4 z = make_float4(0.f, 0.f, 0.f, 0.f);
        for (int e = tid; e < 1024; e += 256) ((float4*)pa)[e] = z;
        if (tid < 64) g_pl[slot * 64 + tid] = 0.f;
        return;
    }

    const float* qp = g_q + (size_t)b * TT * HH;
    const float* kp = g_k + (size_t)b * TT * HH;
    const float* vp = g_v + (size_t)b * TT * HH;

    // Stage Q (tf32-rounded) into Ps region, then load register fragments.
#pragma unroll
    for (int it = 0; it < 4; it++) {
        int idx = it * 256 + tid;
        int n  = idx >> 4;
        int h4 = (idx & 15) * 4;
        float4 v = *(const float4*)&qp[(size_t)(q0 + n) * HH + h4];
        uint4 u = make_uint4(tf32r(v.x), tf32r(v.y), tf32r(v.z), tf32r(v.w));
        *(uint4*)&Ps[n * 68 + h4] = u;
    }
    __syncthreads();

    uint32_t qa[8][4];
    {
        const uint32_t* Pu = (const uint32_t*)Ps;
#pragma unroll
        for (int kk = 0; kk < 8; kk++) {
            qa[kk][0] = Pu[r0 * 68 + kk * 8 + t];
            qa[kk][1] = Pu[(r0 + 8) * 68 + kk * 8 + t];
            qa[kk][2] = Pu[r0 * 68 + kk * 8 + t + 4];
            qa[kk][3] = Pu[(r0 + 8) * 68 + kk * 8 + t + 4];
        }
    }
    __syncthreads();   // Q frag reads done before Ps is overwritten by softmax

    // Stage first chunk's K/V
    {
        const int s0 = lo * 64;
#pragma unroll
        for (int it = 0; it < 4; it++) {
            int idx = it * 256 + tid;
            int n  = idx >> 4;
            int h4 = (idx & 15) * 4;
            float4 kv = *(const float4*)&kp[(size_t)(s0 + n) * HH + h4];
            *(uint4*)&Ks[n * 68 + h4] =
                make_uint4(tf32r(kv.x), tf32r(kv.y), tf32r(kv.z), tf32r(kv.w));
            float4 vv = *(const float4*)&vp[(size_t)(s0 + n) * HH + h4];
            *(uint4*)&Vs[n * 72 + h4] =
                make_uint4(tf32r(vv.x), tf32r(vv.y), tf32r(vv.z), tf32r(vv.w));
        }
    }
    __syncthreads();

    float oc[4][4];
#pragma unroll
    for (int i = 0; i < 4; i++)
#pragma unroll
        for (int j = 0; j < 4; j++) oc[i][j] = 0.f;
    float lr0 = 0.f, lr1 = 0.f;

    for (int ck = lo; ck < hi; ck++) {
        // prefetch next chunk's K/V into registers (latency hidden by MMAs)
        float4 pk[4], pv[4];
        const bool pre = (ck + 1 < hi);
        if (pre) {
            const int s1 = (ck + 1) * 64;
#pragma unroll
            for (int it = 0; it < 4; it++) {
                int idx = it * 256 + tid;
                int n  = idx >> 4;
                int h4 = (idx & 15) * 4;
                pk[it] = *(const float4*)&kp[(size_t)(s1 + n) * HH + h4];
                pv[it] = *(const float4*)&vp[(size_t)(s1 + n) * HH + h4];
            }
        }

        // GEMM1: S[m][n] = Q x K^T (k = h = 64 -> 8 k-steps)
        float sc[4][4];
#pragma unroll
        for (int i = 0; i < 4; i++)
#pragma unroll
            for (int j = 0; j < 4; j++) sc[i][j] = 0.f;

        const uint32_t* Ku = (const uint32_t*)Ks;
#pragma unroll
        for (int kk = 0; kk < 8; kk++) {
#pragma unroll
            for (int nt = 0; nt < 4; nt++) {
                uint32_t b0 = Ku[(nb + nt * 8 + g) * 68 + kk * 8 + t];
                uint32_t b1 = Ku[(nb + nt * 8 + g) * 68 + kk * 8 + t + 4];
                mma8(sc[nt], qa[kk][0], qa[kk][1], qa[kk][2], qa[kk][3], b0, b1);
            }
        }

        // softmax: P = exp2(S) with causal mask on diagonal chunk
        const int diag = (ck == qt);
#pragma unroll
        for (int nt = 0; nt < 4; nt++) {
            int c0 = nb + nt * 8 + 2 * t;
            float p0 = ex2(sc[nt][0]);
            float p1 = ex2(sc[nt][1]);
            float p2 = ex2(sc[nt][2]);
            float p3 = ex2(sc[nt][3]);
            if (diag) {
                if (c0 > r0)     p0 = 0.f;
                if (c0 + 1 > r0) p1 = 0.f;
                if (c0 > r0 + 8)     p2 = 0.f;
                if (c0 + 1 > r0 + 8) p3 = 0.f;
            }
            uint32_t u0 = tf32r(p0), u1 = tf32r(p1), u2 = tf32r(p2), u3 = tf32r(p3);
            lr0 += __uint_as_float(u0) + __uint_as_float(u1);
            lr1 += __uint_as_float(u2) + __uint_as_float(u3);
            *(uint2*)&Ps[r0 * 68 + c0]       = make_uint2(u0, u1);
            *(uint2*)&Ps[(r0 + 8) * 68 + c0] = make_uint2(u2, u3);
        }
        __syncthreads();   // all P visible before cross-warp GEMM2

        // GEMM2: O[m][h] += P x V (k = s = 64 -> 8 k-steps)
        const uint32_t* Pu = (const uint32_t*)Ps;
        const uint32_t* Vu = (const uint32_t*)Vs;
#pragma unroll
        for (int kk = 0; kk < 8; kk++) {
            uint32_t a0 = Pu[r0 * 68 + kk * 8 + t];
            uint32_t a1 = Pu[(r0 + 8) * 68 + kk * 8 + t];
            uint32_t a2 = Pu[r0 * 68 + kk * 8 + t + 4];
            uint32_t a3 = Pu[(r0 + 8) * 68 + kk * 8 + t + 4];
#pragma unroll
            for (int nt = 0; nt < 4; nt++) {
                uint32_t b0 = Vu[(kk * 8 + t) * 72 + nb + nt * 8 + g];
                uint32_t b1 = Vu[(kk * 8 + t + 4) * 72 + nb + nt * 8 + g];
                mma8(oc[nt], a0, a1, a2, a3, b0, b1);
            }
        }
        __syncthreads();   // GEMM2 reads done before restaging K/V

        if (pre) {
#pragma unroll
            for (int it = 0; it < 4; it++) {
                int idx = it * 256 + tid;
                int n  = idx >> 4;
                int h4 = (idx & 15) * 4;
                *(uint4*)&Ks[n * 68 + h4] =
                    make_uint4(tf32r(pk[it].x), tf32r(pk[it].y), tf32r(pk[it].z), tf32r(pk[it].w));
                *(uint4*)&Vs[n * 72 + h4] =
                    make_uint4(tf32r(pv[it].x), tf32r(pv[it].y), tf32r(pv[it].z), tf32r(pv[it].w));
            }
            __syncthreads();
        }
    }

    // row-sum reduction: across 4 lanes of the group, then across n-half warps
    lr0 += __shfl_xor_sync(0xffffffffu, lr0, 1);
    lr0 += __shfl_xor_sync(0xffffffffu, lr0, 2);
    lr1 += __shfl_xor_sync(0xffffffffu, lr1, 1);
    lr1 += __shfl_xor_sync(0xffffffffu, lr1, 2);
    if (t == 0) {
        lbuf[nh * 64 + r0]     = lr0;
        lbuf[nh * 64 + r0 + 8] = lr1;
    }
    __syncthreads();

    // write partials
#pragma unroll
    for (int nt = 0; nt < 4; nt++) {
        int col = nb + nt * 8 + 2 * t;
        *(float2*)&pa[r0 * 64 + col]       = make_float2(oc[nt][0], oc[nt][1]);
        *(float2*)&pa[(r0 + 8) * 64 + col] = make_float2(oc[nt][2], oc[nt][3]);
    }
    if (tid < 64) g_pl[slot * 64 + tid] = lbuf[tid] + lbuf[64 + tid];
}

// ---------------------------------------------------------------------------
// Kernel 3: merge key-split partials (plain sums) and normalize.
// ---------------------------------------------------------------------------
__global__ __launch_bounds__(256)
void combine_kernel(float* __restrict__ out) {
    const int qt = blockIdx.x;
    const int b  = blockIdx.y;
    const int tid = threadIdx.x;
    const size_t base = (size_t)(b * NQT + qt) * KS;

    __shared__ float ls[64];
    if (tid < 64) {
        float s = 0.f;
#pragma unroll
        for (int sp = 0; sp < KS; sp++) s += g_pl[(base + sp) * 64 + tid];
        ls[tid] = 1.0f / s;
    }
    __syncthreads();

    for (int e = tid; e < 1024; e += 256) {
        const int row = e >> 4;
        float4 a = make_float4(0.f, 0.f, 0.f, 0.f);
#pragma unroll
        for (int sp = 0; sp < KS; sp++) {
            float4 v = ((const float4*)(g_pacc + (base + sp) * 4096))[e];
            a.x += v.x; a.y += v.y; a.z += v.z; a.w += v.w;
        }
        const float inv = ls[row];
        a.x *= inv; a.y *= inv; a.z *= inv; a.w *= inv;
        *(float4*)&out[((size_t)b * TT + qt * 64 + row) * HH + (e & 15) * 4] = a;
    }
}

extern "C" void kernel_launch(void* const* d_in, const int* in_sizes, int n_in,
                              void* d_out, int out_size) {
    const float* x  = (const float*)d_in[0];
    const float* Wk = (const float*)d_in[1];
    const float* Wq = (const float*)d_in[2];
    const float* Wv = (const float*)d_in[3];
    float* out = (float*)d_out;

    proj_kernel<<<dim3(M_TOT / 64, 3), 256>>>(x, Wk, Wq, Wv);

    cudaFuncSetAttribute(attn_kernel,
                         cudaFuncAttributeMaxDynamicSharedMemorySize, ATTN_SMEM);
    attn_kernel<<<dim3(NQT * KS, BB), 256, ATTN_SMEM>>>();

    combine_kernel<<<dim3(NQT, BB), 256>>>(out);
}

// round 8
// speedup vs baseline: 1.2704x; 1.0409x over previous
#include <cuda_runtime.h>
#include <cstdint>

#define BB 4
#define TT 4096
#define CC 768
#define HH 64
#define M_TOT (BB*TT)
#define KS 4
#define NQT 64            // 64-row q-tiles per batch

// ---------------- tf32 mma.sync helpers ----------------
__device__ __forceinline__ uint32_t tf32r(float f) {
    uint32_t r;
    asm("cvt.rna.tf32.f32 %0, %1;" : "=r"(r) : "f"(f));
    return r;
}
__device__ __forceinline__ void mma8(float c[4], uint32_t a0, uint32_t a1,
                                     uint32_t a2, uint32_t a3,
                                     uint32_t b0, uint32_t b1) {
    asm volatile(
        "mma.sync.aligned.m16n8k8.row.col.f32.tf32.tf32.f32 "
        "{%0,%1,%2,%3}, {%4,%5,%6,%7}, {%8,%9}, {%0,%1,%2,%3};"
        : "+f"(c[0]), "+f"(c[1]), "+f"(c[2]), "+f"(c[3])
        : "r"(a0), "r"(a1), "r"(a2), "r"(a3), "r"(b0), "r"(b1));
}
__device__ __forceinline__ float ex2(float x) {
    float r;
    asm("ex2.approx.f32 %0, %1;" : "=f"(r) : "f"(x));
    return r;
}
__device__ __forceinline__ uint32_t smem_u32(const void* p) {
    uint32_t a;
    asm("{ .reg .u64 t; cvta.to.shared.u64 t, %1; cvt.u32.u64 %0, t; }" : "=r"(a) : "l"(p));
    return a;
}
#define CP16(dst, src) asm volatile("cp.async.cg.shared.global [%0], [%1], 16;" :: "r"(dst), "l"(src))
#define CP_COMMIT()    asm volatile("cp.async.commit_group;" ::: "memory")
#define CP_WAIT0()     asm volatile("cp.async.wait_group 0;" ::: "memory")

// ---------------- global scratch ----------------
__device__ float g_q[M_TOT*HH];     // pre-scaled by log2(e)/8
__device__ float g_k[M_TOT*HH];
__device__ float g_v[M_TOT*HH];
__device__ float g_pacc[(size_t)BB*NQT*KS*64*64];   // partial accumulators
__device__ float g_pl[BB*NQT*KS*64];                // partial row sums

// ---------------------------------------------------------------------------
// Kernel 1: QKV projection. CTA tile 128x64, 8 warps of 32x32 (256B frag
// traffic per MMA instead of 384B). cp.async double-buffered staging; tf32
// conversion at fragment load. grid (M_TOT/128, 3), 256 thr.
// Xs[128][36], Ws[32][72], both double-buffered (54KB dynamic smem).
// ---------------------------------------------------------------------------
#define PROJ_SMEM ((2*128*36 + 2*32*72) * 4)

__global__ __launch_bounds__(256)
void proj_kernel(const float* __restrict__ x,
                 const float* __restrict__ Wk,
                 const float* __restrict__ Wq,
                 const float* __restrict__ Wv) {
    extern __shared__ float psm[];
    float* Xb0 = psm;                    // [2][128*36]
    float* Wb0 = psm + 2 * 128 * 36;     // [2][32*72]

    const float* W;
    float* out;
    float scale;
    if (blockIdx.y == 0)      { W = Wk; out = g_k; scale = 1.0f; }
    else if (blockIdx.y == 1) { W = Wq; out = g_q; scale = 0.18033688011112042f; } // log2(e)/8
    else                      { W = Wv; out = g_v; scale = 1.0f; }

    const int m0   = blockIdx.x * 128;
    const int tid  = threadIdx.x;
    const int wid  = tid >> 5;
    const int lane = tid & 31;
    const int g    = lane >> 2;
    const int t    = lane & 3;
    const int ms   = wid >> 1;           // 0..3: 32-row slab
    const int nn   = (wid & 1) * 32;     // 0/32: 32-col half

    // staging coords
    const int xr = tid >> 3;             // + it*32
    const int xf = (tid & 7) * 4;
    const int wr = tid >> 4;             // + it*16
    const int wh = (tid & 15) * 4;

    float oc[2][4][4];
#pragma unroll
    for (int mt = 0; mt < 2; mt++)
#pragma unroll
        for (int i = 0; i < 4; i++)
#pragma unroll
            for (int j = 0; j < 4; j++) oc[mt][i][j] = 0.f;

    // stage chunk 0 into buffer 0
    {
        uint32_t xb = smem_u32(Xb0);
        uint32_t wb = smem_u32(Wb0);
#pragma unroll
        for (int it = 0; it < 4; it++)
            CP16(xb + ((it * 32 + xr) * 36 + xf) * 4,
                 &x[(size_t)(m0 + it * 32 + xr) * CC + xf]);
#pragma unroll
        for (int it = 0; it < 2; it++)
            CP16(wb + ((it * 16 + wr) * 72 + wh) * 4,
                 &W[(size_t)(it * 16 + wr) * HH + wh]);
        CP_COMMIT();
    }

    int buf = 0;
    for (int k0 = 0; k0 < CC; k0 += 32) {
        CP_WAIT0();
        __syncthreads();

        if (k0 + 32 < CC) {
            uint32_t xb = smem_u32(Xb0 + (buf ^ 1) * 128 * 36);
            uint32_t wb = smem_u32(Wb0 + (buf ^ 1) * 32 * 72);
#pragma unroll
            for (int it = 0; it < 4; it++)
                CP16(xb + ((it * 32 + xr) * 36 + xf) * 4,
                     &x[(size_t)(m0 + it * 32 + xr) * CC + k0 + 32 + xf]);
#pragma unroll
            for (int it = 0; it < 2; it++)
                CP16(wb + ((it * 16 + wr) * 72 + wh) * 4,
                     &W[(size_t)(k0 + 32 + it * 16 + wr) * HH + wh]);
            CP_COMMIT();
        }

        const float* Xc = Xb0 + buf * 128 * 36;
        const float* Wc = Wb0 + buf * 32 * 72;
#pragma unroll
        for (int kk = 0; kk < 4; kk++) {
            uint32_t a[2][4];
#pragma unroll
            for (int mt = 0; mt < 2; mt++) {
                int rb = ms * 32 + mt * 16 + g;
                a[mt][0] = tf32r(Xc[rb * 36 + kk * 8 + t]);
                a[mt][1] = tf32r(Xc[(rb + 8) * 36 + kk * 8 + t]);
                a[mt][2] = tf32r(Xc[rb * 36 + kk * 8 + t + 4]);
                a[mt][3] = tf32r(Xc[(rb + 8) * 36 + kk * 8 + t + 4]);
            }
#pragma unroll
            for (int nt = 0; nt < 4; nt++) {
                uint32_t b0 = tf32r(Wc[(kk * 8 + t) * 72 + nn + nt * 8 + g]);
                uint32_t b1 = tf32r(Wc[(kk * 8 + t + 4) * 72 + nn + nt * 8 + g]);
                mma8(oc[0][nt], a[0][0], a[0][1], a[0][2], a[0][3], b0, b1);
                mma8(oc[1][nt], a[1][0], a[1][1], a[1][2], a[1][3], b0, b1);
            }
        }
        buf ^= 1;
    }

#pragma unroll
    for (int mt = 0; mt < 2; mt++) {
        int r0 = m0 + ms * 32 + mt * 16 + g;
#pragma unroll
        for (int nt = 0; nt < 4; nt++) {
            int col = nn + nt * 8 + 2 * t;
            *(float2*)&out[(size_t)r0 * HH + col] =
                make_float2(oc[mt][nt][0] * scale, oc[mt][nt][1] * scale);
            *(float2*)&out[(size_t)(r0 + 8) * HH + col] =
                make_float2(oc[mt][nt][2] * scale, oc[mt][nt][3] * scale);
        }
    }
}

// ---------------------------------------------------------------------------
// Kernel 2: tf32 mma.sync flash attention partials (fixed-offset softmax,
// no rescale). cp.async double-buffered K/V staging (raw fp32 in smem,
// tf32 cvt at fragment load); 2 syncs per chunk.
// CTA = (batch, 64-row q-tile, key-split). 8 warps: 16m x 32n slabs.
// ---------------------------------------------------------------------------
#define ATTN_SMEM ((2*64*68 + 2*64*72 + 64*68 + 128) * 4)   // 89.6KB

__global__ __launch_bounds__(256, 2)
void attn_kernel() {
    extern __shared__ float sm[];
    float* Ks0  = sm;                    // [2][64*68]
    float* Vs0  = sm + 2 * 64 * 68;      // [2][64*72]
    float* Ps   = sm + 2 * 64 * 68 + 2 * 64 * 72;   // [64*68]
    float* lbuf = Ps + 64 * 68;          // [2][64]

    const int tid  = threadIdx.x;
    const int wid  = tid >> 5;
    const int lane = tid & 31;
    const int g    = lane >> 2;
    const int t    = lane & 3;
    const int ms   = wid >> 1;
    const int nh   = wid & 1;
    const int nb   = nh * 32;
    const int r0   = ms * 16 + g;

    const int b     = blockIdx.y;
    const int qt    = NQT - 1 - (blockIdx.x >> 2);   // heavy tiles first
    const int split = blockIdx.x & (KS - 1);
    const int q0    = qt * 64;
    const int nch   = qt + 1;
    const int lo    = (split * nch) / KS;
    const int hi    = ((split + 1) * nch) / KS;
    const size_t slot = (size_t)(b * NQT + qt) * KS + split;
    float* pa = g_pacc + slot * 4096;

    if (lo >= hi) {
        float4 z = make_float4(0.f, 0.f, 0.f, 0.f);
        for (int e = tid; e < 1024; e += 256) ((float4*)pa)[e] = z;
        if (tid < 64) g_pl[slot * 64 + tid] = 0.f;
        return;
    }

    const float* qp = g_q + (size_t)b * TT * HH;
    const float* kp = g_k + (size_t)b * TT * HH;
    const float* vp = g_v + (size_t)b * TT * HH;

    // staging coords (per thread, 4 iterations each for K and V)
    const int sn = tid >> 4;             // + it*16
    const int sh = (tid & 15) * 4;

    // kick off chunk lo's K/V staging
    {
        uint32_t kb = smem_u32(Ks0);
        uint32_t vb = smem_u32(Vs0);
        const int s0 = lo * 64;
#pragma unroll
        for (int it = 0; it < 4; it++) {
            int n = it * 16 + sn;
            CP16(kb + (n * 68 + sh) * 4, &kp[(size_t)(s0 + n) * HH + sh]);
            CP16(vb + (n * 72 + sh) * 4, &vp[(size_t)(s0 + n) * HH + sh]);
        }
        CP_COMMIT();
    }

    // Stage Q (tf32-rounded) into Ps region, then extract register fragments.
#pragma unroll
    for (int it = 0; it < 4; it++) {
        int n = it * 16 + sn;
        float4 v = *(const float4*)&qp[(size_t)(q0 + n) * HH + sh];
        *(uint4*)&Ps[n * 68 + sh] =
            make_uint4(tf32r(v.x), tf32r(v.y), tf32r(v.z), tf32r(v.w));
    }
    __syncthreads();

    uint32_t qa[8][4];
    {
        const uint32_t* Pu = (const uint32_t*)Ps;
#pragma unroll
        for (int kk = 0; kk < 8; kk++) {
            qa[kk][0] = Pu[r0 * 68 + kk * 8 + t];
            qa[kk][1] = Pu[(r0 + 8) * 68 + kk * 8 + t];
            qa[kk][2] = Pu[r0 * 68 + kk * 8 + t + 4];
            qa[kk][3] = Pu[(r0 + 8) * 68 + kk * 8 + t + 4];
        }
    }

    float oc[4][4];
#pragma unroll
    for (int i = 0; i < 4; i++)
#pragma unroll
        for (int j = 0; j < 4; j++) oc[i][j] = 0.f;
    float lr0 = 0.f, lr1 = 0.f;

    int buf = 0;
    for (int ck = lo; ck < hi; ck++) {
        CP_WAIT0();
        __syncthreads();   // cur K/V visible; prev GEMM2 (P, V reads) done; Q frags extracted

        if (ck + 1 < hi) {
            uint32_t kb = smem_u32(Ks0 + (buf ^ 1) * 64 * 68);
            uint32_t vb = smem_u32(Vs0 + (buf ^ 1) * 64 * 72);
            const int s1 = (ck + 1) * 64;
#pragma unroll
            for (int it = 0; it < 4; it++) {
                int n = it * 16 + sn;
                CP16(kb + (n * 68 + sh) * 4, &kp[(size_t)(s1 + n) * HH + sh]);
                CP16(vb + (n * 72 + sh) * 4, &vp[(size_t)(s1 + n) * HH + sh]);
            }
            CP_COMMIT();
        }

        const float* Kc = Ks0 + buf * 64 * 68;
        const float* Vc = Vs0 + buf * 64 * 72;

        // GEMM1: S = Q x K^T (8 k-steps; K frags cvt'd at load)
        float sc[4][4];
#pragma unroll
        for (int i = 0; i < 4; i++)
#pragma unroll
            for (int j = 0; j < 4; j++) sc[i][j] = 0.f;
#pragma unroll
        for (int kk = 0; kk < 8; kk++) {
#pragma unroll
            for (int nt = 0; nt < 4; nt++) {
                uint32_t b0 = tf32r(Kc[(nb + nt * 8 + g) * 68 + kk * 8 + t]);
                uint32_t b1 = tf32r(Kc[(nb + nt * 8 + g) * 68 + kk * 8 + t + 4]);
                mma8(sc[nt], qa[kk][0], qa[kk][1], qa[kk][2], qa[kk][3], b0, b1);
            }
        }

        // softmax: P = exp2(S), causal mask on diagonal chunk
        const int diag = (ck == qt);
#pragma unroll
        for (int nt = 0; nt < 4; nt++) {
            int c0 = nb + nt * 8 + 2 * t;
            float p0 = ex2(sc[nt][0]);
            float p1 = ex2(sc[nt][1]);
            float p2 = ex2(sc[nt][2]);
            float p3 = ex2(sc[nt][3]);
            if (diag) {
                if (c0 > r0)     p0 = 0.f;
                if (c0 + 1 > r0) p1 = 0.f;
                if (c0 > r0 + 8)     p2 = 0.f;
                if (c0 + 1 > r0 + 8) p3 = 0.f;
            }
            uint32_t u0 = tf32r(p0), u1 = tf32r(p1), u2 = tf32r(p2), u3 = tf32r(p3);
            lr0 += __uint_as_float(u0) + __uint_as_float(u1);
            lr1 += __uint_as_float(u2) + __uint_as_float(u3);
            *(uint2*)&Ps[r0 * 68 + c0]       = make_uint2(u0, u1);
            *(uint2*)&Ps[(r0 + 8) * 68 + c0] = make_uint2(u2, u3);
        }
        __syncthreads();   // all P visible before cross-warp GEMM2

        // GEMM2: O += P x V (8 k-steps; V frags cvt'd at load)
        const uint32_t* Pu = (const uint32_t*)Ps;
#pragma unroll
        for (int kk = 0; kk < 8; kk++) {
            uint32_t a0 = Pu[r0 * 68 + kk * 8 + t];
            uint32_t a1 = Pu[(r0 + 8) * 68 + kk * 8 + t];
            uint32_t a2 = Pu[r0 * 68 + kk * 8 + t + 4];
            uint32_t a3 = Pu[(r0 + 8) * 68 + kk * 8 + t + 4];
#pragma unroll
            for (int nt = 0; nt < 4; nt++) {
                uint32_t b0 = tf32r(Vc[(kk * 8 + t) * 72 + nb + nt * 8 + g]);
                uint32_t b1 = tf32r(Vc[(kk * 8 + t + 4) * 72 + nb + nt * 8 + g]);
                mma8(oc[nt], a0, a1, a2, a3, b0, b1);
            }
        }
        buf ^= 1;
    }

    // row-sum reduction
    lr0 += __shfl_xor_sync(0xffffffffu, lr0, 1);
    lr0 += __shfl_xor_sync(0xffffffffu, lr0, 2);
    lr1 += __shfl_xor_sync(0xffffffffu, lr1, 1);
    lr1 += __shfl_xor_sync(0xffffffffu, lr1, 2);
    if (t == 0) {
        lbuf[nh * 64 + r0]     = lr0;
        lbuf[nh * 64 + r0 + 8] = lr1;
    }
    __syncthreads();

    // write partials
#pragma unroll
    for (int nt = 0; nt < 4; nt++) {
        int col = nb + nt * 8 + 2 * t;
        *(float2*)&pa[r0 * 64 + col]       = make_float2(oc[nt][0], oc[nt][1]);
        *(float2*)&pa[(r0 + 8) * 64 + col] = make_float2(oc[nt][2], oc[nt][3]);
    }
    if (tid < 64) g_pl[slot * 64 + tid] = lbuf[tid] + lbuf[64 + tid];
}

// ---------------------------------------------------------------------------
// Kernel 3: merge key-split partials (plain sums) and normalize.
// ---------------------------------------------------------------------------
__global__ __launch_bounds__(256)
void combine_kernel(float* __restrict__ out) {
    const int qt = blockIdx.x;
    const int b  = blockIdx.y;
    const int tid = threadIdx.x;
    const size_t base = (size_t)(b * NQT + qt) * KS;

    __shared__ float ls[64];
    if (tid < 64) {
        float s = 0.f;
#pragma unroll
        for (int sp = 0; sp < KS; sp++) s += g_pl[(base + sp) * 64 + tid];
        ls[tid] = 1.0f / s;
    }
    __syncthreads();

    for (int e = tid; e < 1024; e += 256) {
        const int row = e >> 4;
        float4 a = make_float4(0.f, 0.f, 0.f, 0.f);
#pragma unroll
        for (int sp = 0; sp < KS; sp++) {
            float4 v = ((const float4*)(g_pacc + (base + sp) * 4096))[e];
            a.x += v.x; a.y += v.y; a.z += v.z; a.w += v.w;
        }
        const float inv = ls[row];
        a.x *= inv; a.y *= inv; a.z *= inv; a.w *= inv;
        *(float4*)&out[((size_t)b * TT + qt * 64 + row) * HH + (e & 15) * 4] = a;
    }
}

extern "C" void kernel_launch(void* const* d_in, const int* in_sizes, int n_in,
                              void* d_out, int out_size) {
    const float* x  = (const float*)d_in[0];
    const float* Wk = (const float*)d_in[1];
    const float* Wq = (const float*)d_in[2];
    const float* Wv = (const float*)d_in[3];
    float* out = (float*)d_out;

    cudaFuncSetAttribute(proj_kernel,
                         cudaFuncAttributeMaxDynamicSharedMemorySize, PROJ_SMEM);
    proj_kernel<<<dim3(M_TOT / 128, 3), 256, PROJ_SMEM>>>(x, Wk, Wq, Wv);

    cudaFuncSetAttribute(attn_kernel,
                         cudaFuncAttributeMaxDynamicSharedMemorySize, ATTN_SMEM);
    attn_kernel<<<dim3(NQT * KS, BB), 256, ATTN_SMEM>>>();

    combine_kernel<<<dim3(NQT, BB), 256>>>(out);
}

// round 9
// speedup vs baseline: 1.2914x; 1.0165x over previous
#include <cuda_runtime.h>
#include <cstdint>

#define BB 4
#define TT 4096
#define CC 768
#define HH 64
#define M_TOT (BB*TT)
#define KS 4
#define MT 128
#define NQT2 (TT/MT)      // 32 q-tiles per batch

// ---------------- tf32 mma.sync helpers ----------------
__device__ __forceinline__ uint32_t tf32r(float f) {
    uint32_t r;
    asm("cvt.rna.tf32.f32 %0, %1;" : "=r"(r) : "f"(f));
    return r;
}
__device__ __forceinline__ void mma8(float c[4], uint32_t a0, uint32_t a1,
                                     uint32_t a2, uint32_t a3,
                                     uint32_t b0, uint32_t b1) {
    asm volatile(
        "mma.sync.aligned.m16n8k8.row.col.f32.tf32.tf32.f32 "
        "{%0,%1,%2,%3}, {%4,%5,%6,%7}, {%8,%9}, {%0,%1,%2,%3};"
        : "+f"(c[0]), "+f"(c[1]), "+f"(c[2]), "+f"(c[3])
        : "r"(a0), "r"(a1), "r"(a2), "r"(a3), "r"(b0), "r"(b1));
}
__device__ __forceinline__ float ex2(float x) {
    float r;
    asm("ex2.approx.f32 %0, %1;" : "=f"(r) : "f"(x));
    return r;
}
__device__ __forceinline__ uint32_t smem_u32(const void* p) {
    uint32_t a;
    asm("{ .reg .u64 t; cvta.to.shared.u64 t, %1; cvt.u32.u64 %0, t; }" : "=r"(a) : "l"(p));
    return a;
}
#define CP16(dst, src) asm volatile("cp.async.cg.shared.global [%0], [%1], 16;" :: "r"(dst), "l"(src))
#define CP_COMMIT()    asm volatile("cp.async.commit_group;" ::: "memory")
#define CP_WAIT0()     asm volatile("cp.async.wait_group 0;" ::: "memory")
#define CP_WAIT1()     asm volatile("cp.async.wait_group 1;" ::: "memory")

// ---------------- global scratch (q/k/v stored pre-rounded to tf32) -------
__device__ float g_q[M_TOT*HH];     // pre-scaled by log2(e)/8, tf32-rounded
__device__ float g_k[M_TOT*HH];     // tf32-rounded
__device__ float g_v[M_TOT*HH];     // tf32-rounded
__device__ float g_pacc[(size_t)BB*NQT2*KS*MT*HH];  // 16.8 MB partials
__device__ float g_pl[BB*NQT2*KS*MT];               // partial row sums

// ---------------------------------------------------------------------------
// Kernel 1: QKV projection (unchanged R8 structure; epilogue now stores
// tf32-rounded values so attn needs no cvt at fragment load).
// CTA tile 128x64, 8 warps of 32x32, cp.async double-buffered.
// ---------------------------------------------------------------------------
#define PROJ_SMEM ((2*128*36 + 2*32*72) * 4)

__global__ __launch_bounds__(256)
void proj_kernel(const float* __restrict__ x,
                 const float* __restrict__ Wk,
                 const float* __restrict__ Wq,
                 const float* __restrict__ Wv) {
    extern __shared__ float psm[];
    float* Xb0 = psm;
    float* Wb0 = psm + 2 * 128 * 36;

    const float* W;
    float* out;
    float scale;
    if (blockIdx.y == 0)      { W = Wk; out = g_k; scale = 1.0f; }
    else if (blockIdx.y == 1) { W = Wq; out = g_q; scale = 0.18033688011112042f; } // log2(e)/8
    else                      { W = Wv; out = g_v; scale = 1.0f; }

    const int m0   = blockIdx.x * 128;
    const int tid  = threadIdx.x;
    const int wid  = tid >> 5;
    const int lane = tid & 31;
    const int g    = lane >> 2;
    const int t    = lane & 3;
    const int ms   = wid >> 1;
    const int nn   = (wid & 1) * 32;

    const int xr = tid >> 3;
    const int xf = (tid & 7) * 4;
    const int wr = tid >> 4;
    const int wh = (tid & 15) * 4;

    float oc[2][4][4];
#pragma unroll
    for (int mt = 0; mt < 2; mt++)
#pragma unroll
        for (int i = 0; i < 4; i++)
#pragma unroll
            for (int j = 0; j < 4; j++) oc[mt][i][j] = 0.f;

    {
        uint32_t xb = smem_u32(Xb0);
        uint32_t wb = smem_u32(Wb0);
#pragma unroll
        for (int it = 0; it < 4; it++)
            CP16(xb + ((it * 32 + xr) * 36 + xf) * 4,
                 &x[(size_t)(m0 + it * 32 + xr) * CC + xf]);
#pragma unroll
        for (int it = 0; it < 2; it++)
            CP16(wb + ((it * 16 + wr) * 72 + wh) * 4,
                 &W[(size_t)(it * 16 + wr) * HH + wh]);
        CP_COMMIT();
    }

    int buf = 0;
    for (int k0 = 0; k0 < CC; k0 += 32) {
        CP_WAIT0();
        __syncthreads();

        if (k0 + 32 < CC) {
            uint32_t xb = smem_u32(Xb0 + (buf ^ 1) * 128 * 36);
            uint32_t wb = smem_u32(Wb0 + (buf ^ 1) * 32 * 72);
#pragma unroll
            for (int it = 0; it < 4; it++)
                CP16(xb + ((it * 32 + xr) * 36 + xf) * 4,
                     &x[(size_t)(m0 + it * 32 + xr) * CC + k0 + 32 + xf]);
#pragma unroll
            for (int it = 0; it < 2; it++)
                CP16(wb + ((it * 16 + wr) * 72 + wh) * 4,
                     &W[(size_t)(k0 + 32 + it * 16 + wr) * HH + wh]);
            CP_COMMIT();
        }

        const float* Xc = Xb0 + buf * 128 * 36;
        const float* Wc = Wb0 + buf * 32 * 72;
#pragma unroll
        for (int kk = 0; kk < 4; kk++) {
            uint32_t a[2][4];
#pragma unroll
            for (int mt = 0; mt < 2; mt++) {
                int rb = ms * 32 + mt * 16 + g;
                a[mt][0] = tf32r(Xc[rb * 36 + kk * 8 + t]);
                a[mt][1] = tf32r(Xc[(rb + 8) * 36 + kk * 8 + t]);
                a[mt][2] = tf32r(Xc[rb * 36 + kk * 8 + t + 4]);
                a[mt][3] = tf32r(Xc[(rb + 8) * 36 + kk * 8 + t + 4]);
            }
#pragma unroll
            for (int nt = 0; nt < 4; nt++) {
                uint32_t b0 = tf32r(Wc[(kk * 8 + t) * 72 + nn + nt * 8 + g]);
                uint32_t b1 = tf32r(Wc[(kk * 8 + t + 4) * 72 + nn + nt * 8 + g]);
                mma8(oc[0][nt], a[0][0], a[0][1], a[0][2], a[0][3], b0, b1);
                mma8(oc[1][nt], a[1][0], a[1][1], a[1][2], a[1][3], b0, b1);
            }
        }
        buf ^= 1;
    }

    // epilogue: tf32-round at store (idempotent vs later rounding)
#pragma unroll
    for (int mt = 0; mt < 2; mt++) {
        int r0 = m0 + ms * 32 + mt * 16 + g;
#pragma unroll
        for (int nt = 0; nt < 4; nt++) {
            int col = nn + nt * 8 + 2 * t;
            float2 v0 = make_float2(__uint_as_float(tf32r(oc[mt][nt][0] * scale)),
                                    __uint_as_float(tf32r(oc[mt][nt][1] * scale)));
            float2 v1 = make_float2(__uint_as_float(tf32r(oc[mt][nt][2] * scale)),
                                    __uint_as_float(tf32r(oc[mt][nt][3] * scale)));
            *(float2*)&out[(size_t)r0 * HH + col]       = v0;
            *(float2*)&out[(size_t)(r0 + 8) * HH + col] = v1;
        }
    }
}

// ---------------------------------------------------------------------------
// Kernel 2: tf32 flash attention partials. MT=128 q-tile, 8 warps (4m x 2n)
// of 32x32 tiles. XOR-swizzled unpadded smem (no cvt: inputs pre-rounded).
// Single-buffer K and V with phase-split cp.async prefetch.
// smem floats: Qs[8192] Ks[4096] Vs[4096] Ps[8192] lbuf[256] = 97KB.
// ---------------------------------------------------------------------------
#define QS_OFF 0
#define KS_OFF 8192
#define VS_OFF 12288
#define PS_OFF 16384
#define LB_OFF 24576
#define ATTN_SMEM ((24576 + 256) * 4)

__global__ __launch_bounds__(256, 2)
void attn_kernel() {
    extern __shared__ float sm[];
    const uint32_t sb = smem_u32(sm);

    const int tid  = threadIdx.x;
    const int wid  = tid >> 5;
    const int lane = tid & 31;
    const int g    = lane >> 2;
    const int t    = lane & 3;
    const int ms   = wid >> 1;           // 0..3: 32-row slab
    const int nh   = wid & 1;            // 0..1: 32-col half
    const int nb   = nh * 32;

    const int b     = blockIdx.y;
    const int qt    = NQT2 - 1 - (blockIdx.x >> 2);  // heavy tiles first
    const int split = blockIdx.x & (KS - 1);
    const int q0    = qt * MT;
    const int nch   = 2 * qt + 2;
    const int lo    = (split * nch) / KS;
    const int hi    = ((split + 1) * nch) / KS;
    const size_t slot = (size_t)(b * NQT2 + qt) * KS + split;
    float* pa = g_pacc + slot * (MT * HH);

    if (lo >= hi) {
        float4 z = make_float4(0.f, 0.f, 0.f, 0.f);
        for (int e = tid; e < MT * HH / 4; e += 256) ((float4*)pa)[e] = z;
        if (tid < MT) g_pl[slot * MT + tid] = 0.f;
        return;
    }

    const float* qp = g_q + (size_t)b * TT * HH;
    const float* kp = g_k + (size_t)b * TT * HH;
    const float* vp = g_v + (size_t)b * TT * HH;

    // staging coords
    const int sn = tid >> 4;             // + it*16
    const int sh = (tid & 15) * 4;

    // prologue: stage Q (8 x cp16) + K(lo) (4 x cp16), one group
    {
#pragma unroll
        for (int it = 0; it < 8; it++) {
            int n = it * 16 + sn;
            CP16(sb + (QS_OFF + n * 64 + (sh ^ ((n & 7) << 2))) * 4,
                 &qp[(size_t)(q0 + n) * HH + sh]);
        }
        const int s0 = lo * 64;
#pragma unroll
        for (int it = 0; it < 4; it++) {
            int n = it * 16 + sn;
            CP16(sb + (KS_OFF + n * 64 + (sh ^ ((n & 7) << 2))) * 4,
                 &kp[(size_t)(s0 + n) * HH + sh]);
        }
        CP_COMMIT();
    }

    const uint32_t* Qu = (const uint32_t*)(sm + QS_OFF);
    const uint32_t* Ku = (const uint32_t*)(sm + KS_OFF);
    const uint32_t* Vu = (const uint32_t*)(sm + VS_OFF);
    const uint32_t* Pu = (const uint32_t*)(sm + PS_OFF);
    float* Ps   = sm + PS_OFF;
    float* lbuf = sm + LB_OFF;

    float oc[2][4][4];
#pragma unroll
    for (int mt = 0; mt < 2; mt++)
#pragma unroll
        for (int i = 0; i < 4; i++)
#pragma unroll
            for (int j = 0; j < 4; j++) oc[mt][i][j] = 0.f;
    float lr[2][2] = {{0.f, 0.f}, {0.f, 0.f}};

    for (int ck = lo; ck < hi; ck++) {
        CP_WAIT0();        // K(ck) (+Q on first iter) arrived
        __syncthreads();   // visible to all; prev GEMM2 done (Ps, Vs free)

        // issue V(ck) prefetch (lands during GEMM1 + softmax)
        {
            const int s0 = ck * 64;
#pragma unroll
            for (int it = 0; it < 4; it++) {
                int n = it * 16 + sn;
                CP16(sb + (VS_OFF + n * 64 + (sh ^ ((n & 3) << 3))) * 4,
                     &vp[(size_t)(s0 + n) * HH + sh]);
            }
            CP_COMMIT();
        }

        // GEMM1: S = Q x K^T  (8 k-steps, no cvt — inputs pre-rounded)
        float sc[2][4][4];
#pragma unroll
        for (int mt = 0; mt < 2; mt++)
#pragma unroll
            for (int i = 0; i < 4; i++)
#pragma unroll
                for (int j = 0; j < 4; j++) sc[mt][i][j] = 0.f;

#pragma unroll
        for (int kk = 0; kk < 8; kk++) {
            const int c0 = (kk * 8 + t) ^ (g << 2);
            const int c4 = (kk * 8 + t + 4) ^ (g << 2);
            uint32_t a[2][4];
#pragma unroll
            for (int mt = 0; mt < 2; mt++) {
                int rb = ms * 32 + mt * 16 + g;
                a[mt][0] = Qu[rb * 64 + c0];
                a[mt][1] = Qu[(rb + 8) * 64 + c0];
                a[mt][2] = Qu[rb * 64 + c4];
                a[mt][3] = Qu[(rb + 8) * 64 + c4];
            }
#pragma unroll
            for (int nt = 0; nt < 4; nt++) {
                int n = nb + nt * 8 + g;
                uint32_t b0 = Ku[n * 64 + c0];
                uint32_t b1 = Ku[n * 64 + c4];
                mma8(sc[0][nt], a[0][0], a[0][1], a[0][2], a[0][3], b0, b1);
                mma8(sc[1][nt], a[1][0], a[1][1], a[1][2], a[1][3], b0, b1);
            }
        }

        // softmax: P = exp2(S), causal mask on diagonal chunks (ck >= 2qt)
        const bool maskc = (ck >= 2 * qt);
#pragma unroll
        for (int mt = 0; mt < 2; mt++) {
            const int R0 = ms * 32 + mt * 16 + g;
#pragma unroll
            for (int nt = 0; nt < 4; nt++) {
                int cl = nb + nt * 8 + 2 * t;
                float p0 = ex2(sc[mt][nt][0]);
                float p1 = ex2(sc[mt][nt][1]);
                float p2 = ex2(sc[mt][nt][2]);
                float p3 = ex2(sc[mt][nt][3]);
                if (maskc) {
                    int i0 = q0 + R0, i1 = i0 + 8;
                    int j0 = ck * 64 + cl;
                    if (j0 > i0)     p0 = 0.f;
                    if (j0 + 1 > i0) p1 = 0.f;
                    if (j0 > i1)     p2 = 0.f;
                    if (j0 + 1 > i1) p3 = 0.f;
                }
                uint32_t u0 = tf32r(p0), u1 = tf32r(p1);
                uint32_t u2 = tf32r(p2), u3 = tf32r(p3);
                lr[mt][0] += __uint_as_float(u0) + __uint_as_float(u1);
                lr[mt][1] += __uint_as_float(u2) + __uint_as_float(u3);
                int pc = cl ^ (g << 2);
                *(uint2*)&Ps[R0 * 64 + pc]       = make_uint2(u0, u1);
                *(uint2*)&Ps[(R0 + 8) * 64 + pc] = make_uint2(u2, u3);
            }
        }
        __syncthreads();   // P visible; K consumed

        // issue K(ck+1) prefetch (lands during GEMM2)
        if (ck + 1 < hi) {
            const int s1 = (ck + 1) * 64;
#pragma unroll
            for (int it = 0; it < 4; it++) {
                int n = it * 16 + sn;
                CP16(sb + (KS_OFF + n * 64 + (sh ^ ((n & 7) << 2))) * 4,
                     &kp[(size_t)(s1 + n) * HH + sh]);
            }
        }
        CP_COMMIT();       // (possibly empty group — keeps wait counts uniform)

        CP_WAIT1();        // V(ck) done (K(ck+1) still in flight)
        __syncthreads();   // V visible to all warps

        // GEMM2: O += P x V  (8 k-steps)
#pragma unroll
        for (int kk = 0; kk < 8; kk++) {
            const int c0 = (kk * 8 + t) ^ (g << 2);
            const int c4 = (kk * 8 + t + 4) ^ (g << 2);
            uint32_t a[2][4];
#pragma unroll
            for (int mt = 0; mt < 2; mt++) {
                int rb = ms * 32 + mt * 16 + g;
                a[mt][0] = Pu[rb * 64 + c0];
                a[mt][1] = Pu[(rb + 8) * 64 + c0];
                a[mt][2] = Pu[rb * 64 + c4];
                a[mt][3] = Pu[(rb + 8) * 64 + c4];
            }
            const int s = kk * 8 + t;
            const int vx = t << 3;
#pragma unroll
            for (int nt = 0; nt < 4; nt++) {
                int c = (nb + nt * 8 + g) ^ vx;
                uint32_t b0 = Vu[s * 64 + c];
                uint32_t b1 = Vu[(s + 4) * 64 + c];
                mma8(oc[0][nt], a[0][0], a[0][1], a[0][2], a[0][3], b0, b1);
                mma8(oc[1][nt], a[1][0], a[1][1], a[1][2], a[1][3], b0, b1);
            }
        }
    }

    // row-sum reduce over t lanes, then across the two nh warps via lbuf
#pragma unroll
    for (int mt = 0; mt < 2; mt++) {
#pragma unroll
        for (int r = 0; r < 2; r++) {
            lr[mt][r] += __shfl_xor_sync(0xffffffffu, lr[mt][r], 1);
            lr[mt][r] += __shfl_xor_sync(0xffffffffu, lr[mt][r], 2);
        }
    }
    __syncthreads();
    if (t == 0) {
#pragma unroll
        for (int mt = 0; mt < 2; mt++) {
            int R0 = ms * 32 + mt * 16 + g;
            lbuf[nh * MT + R0]     = lr[mt][0];
            lbuf[nh * MT + R0 + 8] = lr[mt][1];
        }
    }
    __syncthreads();

    // write partials
#pragma unroll
    for (int mt = 0; mt < 2; mt++) {
        int R0 = ms * 32 + mt * 16 + g;
#pragma unroll
        for (int nt = 0; nt < 4; nt++) {
            int col = nb + nt * 8 + 2 * t;
            *(float2*)&pa[R0 * HH + col]       = make_float2(oc[mt][nt][0], oc[mt][nt][1]);
            *(float2*)&pa[(R0 + 8) * HH + col] = make_float2(oc[mt][nt][2], oc[mt][nt][3]);
        }
    }
    if (tid < MT) g_pl[slot * MT + tid] = lbuf[tid] + lbuf[MT + tid];
}

// ---------------------------------------------------------------------------
// Kernel 3: merge key-split partials (plain sums) and normalize.
// ---------------------------------------------------------------------------
__global__ __launch_bounds__(256)
void combine_kernel(float* __restrict__ out) {
    const int qt = blockIdx.x;
    const int b  = blockIdx.y;
    const int tid = threadIdx.x;
    const size_t base = (size_t)(b * NQT2 + qt) * KS;

    __shared__ float ls[MT];
    if (tid < MT) {
        float s = 0.f;
#pragma unroll
        for (int sp = 0; sp < KS; sp++) s += g_pl[(base + sp) * MT + tid];
        ls[tid] = 1.0f / s;
    }
    __syncthreads();

    for (int e = tid; e < MT * HH / 4; e += 256) {
        const int row = e >> 4;
        float4 a = make_float4(0.f, 0.f, 0.f, 0.f);
#pragma unroll
        for (int sp = 0; sp < KS; sp++) {
            float4 v = ((const float4*)(g_pacc + (base + sp) * (MT * HH)))[e];
            a.x += v.x; a.y += v.y; a.z += v.z; a.w += v.w;
        }
        const float inv = ls[row];
        a.x *= inv; a.y *= inv; a.z *= inv; a.w *= inv;
        *(float4*)&out[((size_t)b * TT + qt * MT + row) * HH + (e & 15) * 4] = a;
    }
}

extern "C" void kernel_launch(void* const* d_in, const int* in_sizes, int n_in,
                              void* d_out, int out_size) {
    const float* x  = (const float*)d_in[0];
    const float* Wk = (const float*)d_in[1];
    const float* Wq = (const float*)d_in[2];
    const float* Wv = (const float*)d_in[3];
    float* out = (float*)d_out;

    cudaFuncSetAttribute(proj_kernel,
                         cudaFuncAttributeMaxDynamicSharedMemorySize, PROJ_SMEM);
    proj_kernel<<<dim3(M_TOT / 128, 3), 256, PROJ_SMEM>>>(x, Wk, Wq, Wv);

    cudaFuncSetAttribute(attn_kernel,
                         cudaFuncAttributeMaxDynamicSharedMemorySize, ATTN_SMEM);
    attn_kernel<<<dim3(NQT2 * KS, BB), 256, ATTN_SMEM>>>();

    combine_kernel<<<dim3(NQT2, BB), 256>>>(out);
}